// round 8
// baseline (speedup 1.0000x reference)
#include <cuda_runtime.h>

// Shapes (fixed by the problem)
#define B_    8
#define T_    12
#define N_    512
#define D_    128
#define H_    8
#define HD_   16
#define X_    64            // H_*B_
#define KTOP_ 153           // int(512*0.3)
#define ATTN_ELEMS 201326592ll   // 64*12*512*512

#define FULLMASK 0xffffffffu

// Scratch: projected q,k in split-head layout [x][t][n][hd]; q pre-scaled by 0.25
__device__ float g_qs[X_*T_*N_*HD_];
__device__ float g_ks[X_*T_*N_*HD_];

// ---------------------------------------------------------------------------
// order-preserving float<->uint key transforms (used only for search bounds)
// ---------------------------------------------------------------------------
__device__ __forceinline__ unsigned flipf(float f) {
    unsigned u = __float_as_uint(f);
    return u ^ ((unsigned)((int)u >> 31) | 0x80000000u);
}
__device__ __forceinline__ float unflipf(unsigned u) {
    unsigned m = 0x80000000u | ~(unsigned)((int)u >> 31);
    return __uint_as_float(u ^ m);
}

// ---------------------------------------------------------------------------
// Kernel 1: fused projections. blockIdx.y selects (q|k|v).
// 64 rows per block, 2 rows per thread (r and r+32). q output pre-scaled by
// 0.25 (= 1/sqrt(HD)) so the attention kernel skips that multiply.
// ---------------------------------------------------------------------------
__global__ __launch_bounds__(256, 2) void proj_kernel(
    const float* __restrict__ qin, const float* __restrict__ kin,
    const float* __restrict__ vin,
    const float* __restrict__ Wq, const float* __restrict__ bq,
    const float* __restrict__ Wk, const float* __restrict__ bk,
    const float* __restrict__ Wv, const float* __restrict__ bv,
    float* __restrict__ out_v)
{
    extern __shared__ float sh[];
    float* shW = sh;            // 128*128 floats, swizzled within rows
    float* shA = sh + 16384;    // 64 rows * 129 (padded) floats

    const float* in; const float* W; const float* bias; float* dst; float scale;
    if (blockIdx.y == 0)      { in = qin; W = Wq; bias = bq; dst = g_qs; scale = 0.25f; }
    else if (blockIdx.y == 1) { in = kin; W = Wk; bias = bk; dst = g_ks; scale = 1.0f; }
    else                      { in = vin; W = Wv; bias = bv; dst = out_v; scale = 1.0f; }

    const int tid = threadIdx.x;

    // Load W (permuted): logical col = 16*cg + 4*c + w -> phys word 4*cg + 32*c + w
    for (int i = tid; i < 16384; i += 256) {
        int k = i >> 7, col = i & 127;
        int cg = col >> 4, c = (col >> 2) & 3, w = col & 3;
        shW[k*128 + cg*4 + c*32 + w] = W[i];
    }
    const size_t base_row = (size_t)blockIdx.x * 64;
    for (int i = tid; i < 2048; i += 256) {        // 64 rows * 32 float4
        int r = i >> 5, c = i & 31;
        float4 v = __ldg((const float4*)(in + base_row*128) + i);
        float* d = shA + r*129 + c*4;
        d[0] = v.x; d[1] = v.y; d[2] = v.z; d[3] = v.w;
    }
    __syncthreads();

    const int r  = tid >> 3;   // 0..31 : rows r and r+32
    const int cg = tid & 7;    // 0..7  : column group == head index

    float acc0[16], acc1[16];
    #pragma unroll
    for (int j = 0; j < 16; j++) {
        float b = __ldg(bias + cg*16 + j);
        acc0[j] = b; acc1[j] = b;
    }

    const float* arow0 = shA + r*129;
    const float* arow1 = shA + (r+32)*129;
    const float* wbase = shW + cg*4;
    #pragma unroll 4
    for (int k = 0; k < 128; k++) {
        const float a0 = arow0[k];
        const float a1 = arow1[k];
        const float4 w0 = *(const float4*)(wbase + k*128);
        const float4 w1 = *(const float4*)(wbase + k*128 + 32);
        const float4 w2 = *(const float4*)(wbase + k*128 + 64);
        const float4 w3 = *(const float4*)(wbase + k*128 + 96);
        acc0[ 0] += a0*w0.x; acc0[ 1] += a0*w0.y; acc0[ 2] += a0*w0.z; acc0[ 3] += a0*w0.w;
        acc0[ 4] += a0*w1.x; acc0[ 5] += a0*w1.y; acc0[ 6] += a0*w1.z; acc0[ 7] += a0*w1.w;
        acc0[ 8] += a0*w2.x; acc0[ 9] += a0*w2.y; acc0[10] += a0*w2.z; acc0[11] += a0*w2.w;
        acc0[12] += a0*w3.x; acc0[13] += a0*w3.y; acc0[14] += a0*w3.z; acc0[15] += a0*w3.w;
        acc1[ 0] += a1*w0.x; acc1[ 1] += a1*w0.y; acc1[ 2] += a1*w0.z; acc1[ 3] += a1*w0.w;
        acc1[ 4] += a1*w1.x; acc1[ 5] += a1*w1.y; acc1[ 6] += a1*w1.z; acc1[ 7] += a1*w1.w;
        acc1[ 8] += a1*w2.x; acc1[ 9] += a1*w2.y; acc1[10] += a1*w2.z; acc1[11] += a1*w2.w;
        acc1[12] += a1*w3.x; acc1[13] += a1*w3.y; acc1[14] += a1*w3.z; acc1[15] += a1*w3.w;
    }

    // Split-head destination: x = h*B + b, h == cg, hd = j
    #pragma unroll
    for (int rr = 0; rr < 2; rr++) {
        const int row = (int)base_row + r + rr*32;
        const int b   = row / (T_*N_);
        const int rem = row - b*(T_*N_);
        const int t   = rem / N_;
        const int n   = rem - t*N_;
        const size_t di = ((((size_t)cg*B_ + b)*T_ + t)*N_ + n)*HD_;
        const float* a = rr ? acc1 : acc0;
        *(float4*)(dst + di     ) = make_float4(a[ 0]*scale,a[ 1]*scale,a[ 2]*scale,a[ 3]*scale);
        *(float4*)(dst + di +  4) = make_float4(a[ 4]*scale,a[ 5]*scale,a[ 6]*scale,a[ 7]*scale);
        *(float4*)(dst + di +  8) = make_float4(a[ 8]*scale,a[ 9]*scale,a[10]*scale,a[11]*scale);
        *(float4*)(dst + di + 12) = make_float4(a[12]*scale,a[13]*scale,a[14]*scale,a[15]*scale);
    }
}

// ---------------------------------------------------------------------------
// Kernel 2: scores + softmax + exact top-k threshold.
// Block: 256 thr (8 warps) = one (x,t), 16 rows (2 rows/warp).
// Selection: exact kth via false-position + bisection hybrid on the flipped
// uint grid, with per-step counts done as FLOAT compares (fma pipe) +
// __reduce_add_sync. Early exit when count==K (kth = warp-min of top set);
// tie-safe fallback terminates when the uint interval reaches width 1.
// ---------------------------------------------------------------------------
__global__ __launch_bounds__(256, 3) void attn_kernel(
    const float* __restrict__ adp, float* __restrict__ out)
{
    extern __shared__ float sh[];
    float* Ksh = sh;                       // 512 * 20 floats = 40960 B

    const int xt   = blockIdx.y;           // 0..767
    const int tile = blockIdx.x;           // 0..31 : 16 rows each
    const int tid  = threadIdx.x;
    const int lane = tid & 31;
    const int wid  = tid >> 5;
    const size_t xtbase = (size_t)xt * N_;

    // Stage K tile (512 x 16 floats) into padded smem
    const float* gk = g_ks + xtbase * HD_;
    for (int i = tid; i < 2048; i += 256) {
        int m = i >> 2, c = i & 3;
        float4 v = __ldg((const float4*)(gk + (size_t)i*4));
        *(float4*)(Ksh + m*20 + c*4) = v;
    }
    __syncthreads();

    const int n0 = tile*16 + wid*2;
    const float* gq = g_qs + (xtbase + n0) * HD_;

    // ---- score phase: 2 rows x 16 m-values per lane, d split in two sweeps
    float s[2][16];
    #pragma unroll
    for (int r = 0; r < 2; r++)
        #pragma unroll
        for (int j = 0; j < 16; j++) s[r][j] = 0.f;

    #pragma unroll
    for (int hh = 0; hh < 2; hh++) {
        float4 qa[2], qb[2];
        #pragma unroll
        for (int r = 0; r < 2; r++) {
            qa[r] = *(const float4*)(gq + r*16 + 8*hh);
            qb[r] = *(const float4*)(gq + r*16 + 8*hh + 4);
        }
        #pragma unroll
        for (int j = 0; j < 16; j++) {
            const int m = lane + 32*j;
            const float* kr = Ksh + m*20 + 8*hh;
            const float4 ka = *(const float4*)kr;
            const float4 kb = *(const float4*)(kr + 4);
            #pragma unroll
            for (int r = 0; r < 2; r++) {
                s[r][j] += qa[r].x*ka.x + qa[r].y*ka.y + qa[r].z*ka.z + qa[r].w*ka.w
                         + qb[r].x*kb.x + qb[r].y*kb.y + qb[r].z*kb.z + qb[r].w*kb.w;
            }
        }
    }

    // ---- finalize: s *= adp  (0.25 already folded into q)
    #pragma unroll
    for (int r = 0; r < 2; r++) {
        const float* arow = adp + (n0 + r)*N_;
        #pragma unroll
        for (int j = 0; j < 16; j++)
            s[r][j] *= __ldg(arow + lane + 32*j);
    }

    // ---- per-row min/max (max for stable exp; both for search bounds)
    float Mf[2], mnf[2];
    #pragma unroll
    for (int r = 0; r < 2; r++) {
        float mx = s[r][0], mn = s[r][0];
        #pragma unroll
        for (int j = 1; j < 16; j++) { mx = fmaxf(mx, s[r][j]); mn = fminf(mn, s[r][j]); }
        #pragma unroll
        for (int d = 16; d; d >>= 1) {
            mx = fmaxf(mx, __shfl_xor_sync(FULLMASK, mx, d));
            mn = fminf(mn, __shfl_xor_sync(FULLMASK, mn, d));
        }
        Mf[r] = mx; mnf[r] = mn;
    }

    // ---- exact kth-largest: hybrid false-position/bisection on uint grid
    unsigned lo[2], hi[2];
    int clo[2], chi[2];
    float kthf[2];
    bool done[2];
    #pragma unroll
    for (int r = 0; r < 2; r++) {
        lo[r] = flipf(mnf[r]); hi[r] = flipf(Mf[r]) + 1u;
        clo[r] = N_; chi[r] = 0; done[r] = false; kthf[r] = mnf[r];
    }

    for (int it = 0; it < 64 && !(done[0] && done[1]); ++it) {
        #pragma unroll
        for (int r = 0; r < 2; r++) {
            if (done[r]) continue;
            if (hi[r] - lo[r] <= 1u) { kthf[r] = unflipf(lo[r]); done[r] = true; continue; }
            unsigned t;
            if (it & 1) {
                t = lo[r] + ((hi[r] - lo[r]) >> 1);            // guaranteed progress
            } else {
                const float f = (float)(clo[r] - KTOP_) / (float)(clo[r] - chi[r]);
                t = lo[r] + (unsigned)((float)(hi[r] - lo[r]) * f);
                const unsigned l1 = lo[r] + 1u, h1 = hi[r] - 1u;
                t = (t < l1) ? l1 : ((t > h1) ? h1 : t);
            }
            const float tf = unflipf(t);
            float cf = 0.f;
            #pragma unroll
            for (int j = 0; j < 16; j++)
                if (s[r][j] >= tf) cf += 1.0f;                  // FSETP + @P FADD (fma pipe)
            const int c = __reduce_add_sync(FULLMASK, (int)cf);
            if (c >= KTOP_) {
                if (c == KTOP_) {                               // kth = min of top set
                    float mk = 3.402823466e38f;
                    #pragma unroll
                    for (int j = 0; j < 16; j++)
                        if (s[r][j] >= tf) mk = fminf(mk, s[r][j]);
                    #pragma unroll
                    for (int d = 16; d; d >>= 1)
                        mk = fminf(mk, __shfl_xor_sync(FULLMASK, mk, d));
                    kthf[r] = mk; done[r] = true;
                } else { lo[r] = t; clo[r] = c; }
            } else { hi[r] = t; chi[r] = c; }
        }
    }
    #pragma unroll
    for (int r = 0; r < 2; r++)
        if (!done[r]) kthf[r] = unflipf(lo[r]);                 // safety net

    // ---- softmax (single exp pass); keep-flag carried in the sign bit
    #pragma unroll
    for (int r = 0; r < 2; r++) {
        const float Mv = Mf[r], kv = kthf[r];
        float sum = 0.f;
        #pragma unroll
        for (int j = 0; j < 16; j++) {
            const float sv = s[r][j];
            const float pv = __expf(sv - Mv);
            sum += pv;
            s[r][j] = (sv >= kv) ? pv : -pv;                    // sign = keep flag
        }
        #pragma unroll
        for (int d = 16; d; d >>= 1) sum += __shfl_xor_sync(FULLMASK, sum, d);
        const float inv = 1.0f / sum;

        float* orow = out + (xtbase + n0 + r) * N_;
        #pragma unroll
        for (int j = 0; j < 16; j++) {
            const float v = s[r][j];
            orow[lane + 32*j] = (v > 0.f) ? v * inv : 0.0f;
        }
    }
}

// ---------------------------------------------------------------------------
extern "C" void kernel_launch(void* const* d_in, const int* in_sizes, int n_in,
                              void* d_out, int out_size)
{
    const float* query = (const float*)d_in[0];
    const float* key   = (const float*)d_in[1];
    const float* value = (const float*)d_in[2];
    const float* adp   = (const float*)d_in[3];
    const float* Wq    = (const float*)d_in[4];
    const float* bq    = (const float*)d_in[5];
    const float* Wk    = (const float*)d_in[6];
    const float* bk    = (const float*)d_in[7];
    const float* Wv    = (const float*)d_in[8];
    const float* bv    = (const float*)d_in[9];

    float* out_attn = (float*)d_out;                 // (64,12,512,512)
    float* out_v    = (float*)d_out + ATTN_ELEMS;    // (64,12,512,16)

    const int proj_smem = (16384 + 64*129) * 4;      // 98560 B
    const int attn_smem = (512*20) * 4;              // 40960 B
    cudaFuncSetAttribute(proj_kernel, cudaFuncAttributeMaxDynamicSharedMemorySize, proj_smem);
    cudaFuncSetAttribute(attn_kernel, cudaFuncAttributeMaxDynamicSharedMemorySize, attn_smem);

    proj_kernel<<<dim3((B_*T_*N_)/64, 3), 256, proj_smem>>>(
        query, key, value, Wq, bq, Wk, bk, Wv, bv, out_v);
    attn_kernel<<<dim3(N_/16, X_*T_), 256, attn_smem>>>(adp, out_attn);
    (void)in_sizes; (void)n_in; (void)out_size;
}

// round 9
// speedup vs baseline: 1.1425x; 1.1425x over previous
#include <cuda_runtime.h>

// Shapes (fixed by the problem)
#define B_    8
#define T_    12
#define N_    512
#define D_    128
#define H_    8
#define HD_   16
#define X_    64            // H_*B_
#define KTOP_ 153           // int(512*0.3)
#define ATTN_ELEMS 201326592ll   // 64*12*512*512

#define FULLMASK 0xffffffffu

// Scratch: projected q,k in split-head layout [x][t][n][hd]; q pre-scaled by 0.25
__device__ float g_qs[X_*T_*N_*HD_];
__device__ float g_ks[X_*T_*N_*HD_];

// ---------------------------------------------------------------------------
// order-preserving float<->uint key transforms (search bounds only)
// ---------------------------------------------------------------------------
__device__ __forceinline__ unsigned flipf(float f) {
    unsigned u = __float_as_uint(f);
    return u ^ ((unsigned)((int)u >> 31) | 0x80000000u);
}
__device__ __forceinline__ float unflipf(unsigned u) {
    unsigned m = 0x80000000u | ~(unsigned)((int)u >> 31);
    return __uint_as_float(u ^ m);
}

// packed f32x2 helpers (Blackwell)
__device__ __forceinline__ unsigned long long pk2(float lo, float hi) {
    unsigned long long d;
    asm("mov.b64 %0, {%1, %2};" : "=l"(d) : "f"(lo), "f"(hi));
    return d;
}
__device__ __forceinline__ float2 up2(unsigned long long v) {
    float2 r;
    asm("mov.b64 {%0, %1}, %2;" : "=f"(r.x), "=f"(r.y) : "l"(v));
    return r;
}
__device__ __forceinline__ unsigned long long fma2(unsigned long long a,
                                                   unsigned long long b,
                                                   unsigned long long c) {
    unsigned long long d;
    asm("fma.rn.f32x2 %0, %1, %2, %3;" : "=l"(d) : "l"(a), "l"(b), "l"(c));
    return d;
}

// ---------------------------------------------------------------------------
// Kernel 1: fused projections. blockIdx.y selects (q|k|v).
// 64 rows per block, 2 rows per thread (r and r+32). q output pre-scaled by
// 0.25 (= 1/sqrt(HD)).
// ---------------------------------------------------------------------------
__global__ __launch_bounds__(256, 2) void proj_kernel(
    const float* __restrict__ qin, const float* __restrict__ kin,
    const float* __restrict__ vin,
    const float* __restrict__ Wq, const float* __restrict__ bq,
    const float* __restrict__ Wk, const float* __restrict__ bk,
    const float* __restrict__ Wv, const float* __restrict__ bv,
    float* __restrict__ out_v)
{
    extern __shared__ float sh[];
    float* shW = sh;            // 128*128 floats, swizzled within rows
    float* shA = sh + 16384;    // 64 rows * 129 (padded) floats

    const float* in; const float* W; const float* bias; float* dst; float scale;
    if (blockIdx.y == 0)      { in = qin; W = Wq; bias = bq; dst = g_qs; scale = 0.25f; }
    else if (blockIdx.y == 1) { in = kin; W = Wk; bias = bk; dst = g_ks; scale = 1.0f; }
    else                      { in = vin; W = Wv; bias = bv; dst = out_v; scale = 1.0f; }

    const int tid = threadIdx.x;

    for (int i = tid; i < 16384; i += 256) {
        int k = i >> 7, col = i & 127;
        int cg = col >> 4, c = (col >> 2) & 3, w = col & 3;
        shW[k*128 + cg*4 + c*32 + w] = W[i];
    }
    const size_t base_row = (size_t)blockIdx.x * 64;
    for (int i = tid; i < 2048; i += 256) {
        int r = i >> 5, c = i & 31;
        float4 v = __ldg((const float4*)(in + base_row*128) + i);
        float* d = shA + r*129 + c*4;
        d[0] = v.x; d[1] = v.y; d[2] = v.z; d[3] = v.w;
    }
    __syncthreads();

    const int r  = tid >> 3;
    const int cg = tid & 7;

    float acc0[16], acc1[16];
    #pragma unroll
    for (int j = 0; j < 16; j++) {
        float b = __ldg(bias + cg*16 + j);
        acc0[j] = b; acc1[j] = b;
    }

    const float* arow0 = shA + r*129;
    const float* arow1 = shA + (r+32)*129;
    const float* wbase = shW + cg*4;
    #pragma unroll 4
    for (int k = 0; k < 128; k++) {
        const float a0 = arow0[k];
        const float a1 = arow1[k];
        const float4 w0 = *(const float4*)(wbase + k*128);
        const float4 w1 = *(const float4*)(wbase + k*128 + 32);
        const float4 w2 = *(const float4*)(wbase + k*128 + 64);
        const float4 w3 = *(const float4*)(wbase + k*128 + 96);
        acc0[ 0] += a0*w0.x; acc0[ 1] += a0*w0.y; acc0[ 2] += a0*w0.z; acc0[ 3] += a0*w0.w;
        acc0[ 4] += a0*w1.x; acc0[ 5] += a0*w1.y; acc0[ 6] += a0*w1.z; acc0[ 7] += a0*w1.w;
        acc0[ 8] += a0*w2.x; acc0[ 9] += a0*w2.y; acc0[10] += a0*w2.z; acc0[11] += a0*w2.w;
        acc0[12] += a0*w3.x; acc0[13] += a0*w3.y; acc0[14] += a0*w3.z; acc0[15] += a0*w3.w;
        acc1[ 0] += a1*w0.x; acc1[ 1] += a1*w0.y; acc1[ 2] += a1*w0.z; acc1[ 3] += a1*w0.w;
        acc1[ 4] += a1*w1.x; acc1[ 5] += a1*w1.y; acc1[ 6] += a1*w1.z; acc1[ 7] += a1*w1.w;
        acc1[ 8] += a1*w2.x; acc1[ 9] += a1*w2.y; acc1[10] += a1*w2.z; acc1[11] += a1*w2.w;
        acc1[12] += a1*w3.x; acc1[13] += a1*w3.y; acc1[14] += a1*w3.z; acc1[15] += a1*w3.w;
    }

    #pragma unroll
    for (int rr = 0; rr < 2; rr++) {
        const int row = (int)base_row + r + rr*32;
        const int b   = row / (T_*N_);
        const int rem = row - b*(T_*N_);
        const int t   = rem / N_;
        const int n   = rem - t*N_;
        const size_t di = ((((size_t)cg*B_ + b)*T_ + t)*N_ + n)*HD_;
        const float* a = rr ? acc1 : acc0;
        *(float4*)(dst + di     ) = make_float4(a[ 0]*scale,a[ 1]*scale,a[ 2]*scale,a[ 3]*scale);
        *(float4*)(dst + di +  4) = make_float4(a[ 4]*scale,a[ 5]*scale,a[ 6]*scale,a[ 7]*scale);
        *(float4*)(dst + di +  8) = make_float4(a[ 8]*scale,a[ 9]*scale,a[10]*scale,a[11]*scale);
        *(float4*)(dst + di + 12) = make_float4(a[12]*scale,a[13]*scale,a[14]*scale,a[15]*scale);
    }
}

// ---------------------------------------------------------------------------
// Exact kth-largest (k = KTOP_) of the 512 values held 16-per-lane in s[].
// Pure clamped false-position on the flipped-uint grid; counts via predicated
// FADD (fma pipe) + REDUX. Exits: c==K (kth = warp-min of top set) or
// interval width 1 (lo is then exactly the kth key). Warp-uniform control.
// ---------------------------------------------------------------------------
__device__ __forceinline__ float kth_largest(const float s[16], float mn, float mx)
{
    unsigned lo = flipf(mn), hi = flipf(mx) + 1u;
    float clo = (float)N_, chi = 0.f;

    for (int it = 0; it < 16; ++it) {
        if (hi - lo <= 1u) return unflipf(lo);
        const float f = (clo - (float)KTOP_) / (clo - chi);
        unsigned t = lo + (unsigned)((float)(hi - lo) * f);
        const unsigned tmin = lo + 1u, tmax = hi - 1u;
        t = (t < tmin) ? tmin : ((t > tmax) ? tmax : t);
        const float tf = unflipf(t);
        float cf = 0.f;
        #pragma unroll
        for (int j = 0; j < 16; j++)
            if (s[j] >= tf) cf += 1.0f;
        const int c = __reduce_add_sync(FULLMASK, (int)cf);
        if (c == KTOP_) {
            float mk = 3.402823466e38f;
            #pragma unroll
            for (int j = 0; j < 16; j++)
                mk = fminf(mk, (s[j] >= tf) ? s[j] : 3.402823466e38f);
            #pragma unroll
            for (int d = 16; d; d >>= 1)
                mk = fminf(mk, __shfl_xor_sync(FULLMASK, mk, d));
            return mk;
        }
        if (c > KTOP_) { lo = t; clo = (float)c; }
        else           { hi = t; chi = (float)c; }
    }
    // fallback: plain bisection to width 1 (rare)
    while (hi - lo > 1u) {
        const unsigned t = lo + ((hi - lo) >> 1);
        const float tf = unflipf(t);
        float cf = 0.f;
        #pragma unroll
        for (int j = 0; j < 16; j++)
            if (s[j] >= tf) cf += 1.0f;
        const int c = __reduce_add_sync(FULLMASK, (int)cf);
        if (c >= KTOP_) lo = t; else hi = t;
    }
    return unflipf(lo);
}

// ---------------------------------------------------------------------------
// Kernel 2: scores + softmax + exact top-k threshold.
// Block: 256 thr (8 warps) = one (x,t), 16 rows (2 rows/warp).
// Score phase uses packed fma.rn.f32x2 along d (even/odd partial sums),
// halving fma-pipe instructions; K smem layout unchanged (d-contiguous).
// ---------------------------------------------------------------------------
__global__ __launch_bounds__(256, 3) void attn_kernel(
    const float* __restrict__ adp, float* __restrict__ out)
{
    extern __shared__ float sh[];
    float* Ksh = sh;                       // 512 * 20 floats = 40960 B

    const int xt   = blockIdx.y;           // 0..767
    const int tile = blockIdx.x;           // 0..31 : 16 rows each
    const int tid  = threadIdx.x;
    const int lane = tid & 31;
    const int wid  = tid >> 5;
    const size_t xtbase = (size_t)xt * N_;

    // Stage K tile (512 x 16 floats) into padded smem (row stride 20)
    const float* gk = g_ks + xtbase * HD_;
    for (int i = tid; i < 2048; i += 256) {
        int m = i >> 2, c = i & 3;
        float4 v = __ldg((const float4*)(gk + (size_t)i*4));
        *(float4*)(Ksh + m*20 + c*4) = v;
    }
    __syncthreads();

    const int n0 = tile*16 + wid*2;
    const float* gq = g_qs + (xtbase + n0) * HD_;

    // q packed as (q_d, q_{d+1}) pairs, per row (8 pairs), reused over all j
    unsigned long long qp0[8], qp1[8];
    {
        const float4 a0 = *(const float4*)(gq     );
        const float4 a1 = *(const float4*)(gq +  4);
        const float4 a2 = *(const float4*)(gq +  8);
        const float4 a3 = *(const float4*)(gq + 12);
        qp0[0]=pk2(a0.x,a0.y); qp0[1]=pk2(a0.z,a0.w);
        qp0[2]=pk2(a1.x,a1.y); qp0[3]=pk2(a1.z,a1.w);
        qp0[4]=pk2(a2.x,a2.y); qp0[5]=pk2(a2.z,a2.w);
        qp0[6]=pk2(a3.x,a3.y); qp0[7]=pk2(a3.z,a3.w);
        const float4 b0 = *(const float4*)(gq + 16);
        const float4 b1 = *(const float4*)(gq + 20);
        const float4 b2 = *(const float4*)(gq + 24);
        const float4 b3 = *(const float4*)(gq + 28);
        qp1[0]=pk2(b0.x,b0.y); qp1[1]=pk2(b0.z,b0.w);
        qp1[2]=pk2(b1.x,b1.y); qp1[3]=pk2(b1.z,b1.w);
        qp1[4]=pk2(b2.x,b2.y); qp1[5]=pk2(b2.z,b2.w);
        qp1[6]=pk2(b3.x,b3.y); qp1[7]=pk2(b3.z,b3.w);
    }

    float s0[16], s1[16];
    #pragma unroll
    for (int j = 0; j < 16; j++) {
        const int m = lane + 32*j;
        const ulonglong2* kp = (const ulonglong2*)(Ksh + m*20);
        const ulonglong2 ka = kp[0];   // d0-3  as pairs
        const ulonglong2 kb = kp[1];   // d4-7
        const ulonglong2 kc = kp[2];   // d8-11
        const ulonglong2 kd = kp[3];   // d12-15

        unsigned long long a0 = fma2(ka.x, qp0[0], 0ull);
        unsigned long long a1 = fma2(ka.x, qp1[0], 0ull);
        a0 = fma2(ka.y, qp0[1], a0);  a1 = fma2(ka.y, qp1[1], a1);
        a0 = fma2(kb.x, qp0[2], a0);  a1 = fma2(kb.x, qp1[2], a1);
        a0 = fma2(kb.y, qp0[3], a0);  a1 = fma2(kb.y, qp1[3], a1);
        a0 = fma2(kc.x, qp0[4], a0);  a1 = fma2(kc.x, qp1[4], a1);
        a0 = fma2(kc.y, qp0[5], a0);  a1 = fma2(kc.y, qp1[5], a1);
        a0 = fma2(kd.x, qp0[6], a0);  a1 = fma2(kd.x, qp1[6], a1);
        a0 = fma2(kd.y, qp0[7], a0);  a1 = fma2(kd.y, qp1[7], a1);
        const float2 f0 = up2(a0);  s0[j] = f0.x + f0.y;
        const float2 f1 = up2(a1);  s1[j] = f1.x + f1.y;
    }

    // ---- finalize: s *= adp  (0.25 folded into q already)
    {
        const float* ar0 = adp + (n0    )*N_;
        const float* ar1 = adp + (n0 + 1)*N_;
        #pragma unroll
        for (int j = 0; j < 16; j++) {
            s0[j] *= __ldg(ar0 + lane + 32*j);
            s1[j] *= __ldg(ar1 + lane + 32*j);
        }
    }

    // ---- per row: min/max, exact kth, softmax, write (sequential rows)
    #pragma unroll 1
    for (int r = 0; r < 2; r++) {
        const float* s = r ? s1 : s0;

        float mx = s[0], mn = s[0];
        #pragma unroll
        for (int j = 1; j < 16; j++) { mx = fmaxf(mx, s[j]); mn = fminf(mn, s[j]); }
        #pragma unroll
        for (int d = 16; d; d >>= 1) {
            mx = fmaxf(mx, __shfl_xor_sync(FULLMASK, mx, d));
            mn = fminf(mn, __shfl_xor_sync(FULLMASK, mn, d));
        }

        const float kv = kth_largest(s, mn, mx);

        float sum = 0.f;
        float p[16];
        #pragma unroll
        for (int j = 0; j < 16; j++) {
            const float sv = s[j];
            const float pv = __expf(sv - mx);
            sum += pv;
            p[j] = (sv >= kv) ? pv : -pv;       // sign carries keep flag
        }
        #pragma unroll
        for (int d = 16; d; d >>= 1) sum += __shfl_xor_sync(FULLMASK, sum, d);
        const float inv = 1.0f / sum;

        float* orow = out + (xtbase + n0 + r) * N_;
        #pragma unroll
        for (int j = 0; j < 16; j++) {
            const float v = p[j];
            orow[lane + 32*j] = (v > 0.f) ? v * inv : 0.0f;
        }
    }
}

// ---------------------------------------------------------------------------
extern "C" void kernel_launch(void* const* d_in, const int* in_sizes, int n_in,
                              void* d_out, int out_size)
{
    const float* query = (const float*)d_in[0];
    const float* key   = (const float*)d_in[1];
    const float* value = (const float*)d_in[2];
    const float* adp   = (const float*)d_in[3];
    const float* Wq    = (const float*)d_in[4];
    const float* bq    = (const float*)d_in[5];
    const float* Wk    = (const float*)d_in[6];
    const float* bk    = (const float*)d_in[7];
    const float* Wv    = (const float*)d_in[8];
    const float* bv    = (const float*)d_in[9];

    float* out_attn = (float*)d_out;                 // (64,12,512,512)
    float* out_v    = (float*)d_out + ATTN_ELEMS;    // (64,12,512,16)

    const int proj_smem = (16384 + 64*129) * 4;      // 98560 B
    const int attn_smem = (512*20) * 4;              // 40960 B
    cudaFuncSetAttribute(proj_kernel, cudaFuncAttributeMaxDynamicSharedMemorySize, proj_smem);
    cudaFuncSetAttribute(attn_kernel, cudaFuncAttributeMaxDynamicSharedMemorySize, attn_smem);

    proj_kernel<<<dim3((B_*T_*N_)/64, 3), 256, proj_smem>>>(
        query, key, value, Wq, bq, Wk, bk, Wv, bv, out_v);
    attn_kernel<<<dim3(N_/16, X_*T_), 256, attn_smem>>>(adp, out_attn);
    (void)in_sizes; (void)n_in; (void)out_size;
}